// round 12
// baseline (speedup 1.0000x reference)
#include <cuda_runtime.h>
#include <math.h>

constexpr int TYc=128, Bc=64, TXc=400, Hc=512, Cc=512, G4c=2048;
constexpr int NBc=128, NTc=1024;

// ---------------- device scratch ----------------
__device__ float g_pctx[(size_t)TXc*Bc*Cc];
__device__ float g_pv  [(size_t)TXc*Bc*Cc];
__device__ float g_xw  [(size_t)TYc*Bc*G4c];   // [t][b][4H]
__device__ float g_xwT [(size_t)TYc*G4c*Bc];   // [t][4H][b]
__device__ float g_bias4[G4c];
__device__ float g_sT[2][1024*Bc];             // [k][b]; 0-511=h, 512-1023=c
__device__ float g_hq [Bc*Cc];
__device__ float g_e  [Bc*8*TXc];
__device__ float g_acc[Bc*TXc];
__device__ float g_ctxbuf[(size_t)TYc*Bc*Cc];  // per-step context (deferred F)
__device__ float g_attbuf[(size_t)TYc*Bc*Cc];  // ctx @ W_concat^T (pre-LN)
__device__ volatile unsigned g_flags[NBc*8];   // global barrier slots
__device__ volatile unsigned g_pflags[NBc*8];  // pair barrier slots

// smem layout (floats)
constexpr int OFF_WHH=0;            // 16x520 = 8320
constexpr int OFF_WCB=8320;         // 4x1040 = 4160
constexpr int OFF_U  =12480;        // 512
constexpr int OFF_WC =12992;        // 512
constexpr int OFF_RED=13504;        // 16384
constexpr int OFF_GATE=29888;       // 1024
constexpr int OFF_SW4=30912;        // 4x408 = 1632
constexpr int SMEM_FLOATS=32544;    // ~130KB

__device__ __forceinline__ float sigf(float x){ return 1.0f/(1.0f+__expf(-x)); }
__device__ __forceinline__ float tanh_acc(float x){
    float e=__expf(2.0f*fabsf(x));
    float r=1.0f-2.0f/(e+1.0f);
    return copysignf(r,x);
}
__device__ __forceinline__ float tanh_fast(float x){
    float r; asm("tanh.approx.f32 %0,%1;":"=f"(r):"f"(x)); return r;
}
// ---- cache-policy loads/stores (policy-register form; direct evict_last
//      qualifier is illegal below 256-bit width on sm_103) ----
__device__ __forceinline__ unsigned long long mk_keep_policy(){
    unsigned long long p;
    asm("createpolicy.fractional.L2::evict_last.b64 %0, 1.0;":"=l"(p));
    return p;
}
__device__ __forceinline__ float ldg_keep(const float* p,unsigned long long pol){
    float v; asm volatile("ld.global.nc.L2::cache_hint.f32 %0,[%1],%2;"
        :"=f"(v):"l"(p),"l"(pol)); return v;
}
__device__ __forceinline__ float4 ldg_keep4(const float* p,unsigned long long pol){
    float4 v; asm volatile("ld.global.nc.L2::cache_hint.v4.f32 {%0,%1,%2,%3},[%4],%5;"
        :"=f"(v.x),"=f"(v.y),"=f"(v.z),"=f"(v.w):"l"(p),"l"(pol)); return v;
}
__device__ __forceinline__ float ldg_stream(const float* p){        // evict-first
    float v; asm volatile("ld.global.cs.f32 %0,[%1];":"=f"(v):"l"(p)); return v;
}
__device__ __forceinline__ void stg_stream(float* p,float v){
    asm volatile("st.global.cs.f32 [%0],%1;"::"l"(p),"f"(v));
}

// ---- flag-based all-to-all grid barrier ----
__device__ __forceinline__ void gsync(unsigned gen){
    __syncthreads();
    if(threadIdx.x==0){ __threadfence(); g_flags[blockIdx.x*8]=gen; }
    if(threadIdx.x<NBc){
        while(g_flags[threadIdx.x*8]<gen){}
    }
    __syncthreads();
    if(threadIdx.x==0) __threadfence();   // drop stale L1 lines
    __syncthreads();
}
// ---- 2-block pair barrier (partner = bk^1) ----
__device__ __forceinline__ void psync(unsigned gen){
    __syncthreads();
    if(threadIdx.x==0){
        __threadfence();
        g_pflags[blockIdx.x*8]=gen;
        while(g_pflags[(blockIdx.x^1)*8]<gen){}
        __threadfence();
    }
    __syncthreads();
}

// ---------------- ONE flattened precompute GEMM (3 sub-problems) -----------
// C[m][n]=sum_k A[m][k]*B[n][k]+bias[n], K=512. Double-buffered.
__global__ void mega_sgemm(const float* __restrict__ ctx,
                           const float* __restrict__ Wc,const float* __restrict__ bc,
                           const float* __restrict__ Wv,const float* __restrict__ bv,
                           const float* __restrict__ yemb,const float* __restrict__ Wih){
    const int K=512;
    int bid=blockIdx.x;
    const float *A,*Bm,*bp; float* Cout;
    int N,bm,bn;
    if(bid<800){        A=ctx;  Bm=Wc;  bp=bc;      Cout=g_pctx; N=512;
                        bm=(bid>>2)*128; bn=(bid&3)*128; }
    else if(bid<1600){  int l=bid-800;
                        A=ctx;  Bm=Wv;  bp=bv;      Cout=g_pv;   N=512;
                        bm=(l>>2)*128; bn=(l&3)*128; }
    else {              int l=bid-1600;
                        A=yemb; Bm=Wih; bp=g_bias4; Cout=g_xw;   N=2048;
                        bm=(l>>4)*128; bn=(l&15)*128; }
    __shared__ float As[8][128], Bs[8][128];
    int tid=threadIdx.x;
    int lr=tid>>1, lc=(tid&1)*4;
    int ty=tid>>4, tx=tid&15;
    float acc[8][8]={};
    const float* Ap=A+(size_t)(bm+lr)*K+lc;
    const float* Bp=Bm+(size_t)(bn+lr)*K+lc;
    float4 a4=*(const float4*)(Ap);
    float4 b4=*(const float4*)(Bp);
    for(int k0=0;k0<K;k0+=8){
        As[lc][lr]=a4.x; As[lc+1][lr]=a4.y; As[lc+2][lr]=a4.z; As[lc+3][lr]=a4.w;
        Bs[lc][lr]=b4.x; Bs[lc+1][lr]=b4.y; Bs[lc+2][lr]=b4.z; Bs[lc+3][lr]=b4.w;
        __syncthreads();
        if(k0+8<K){                       // prefetch next tile during compute
            a4=*(const float4*)(Ap+k0+8);
            b4=*(const float4*)(Bp+k0+8);
        }
#pragma unroll
        for(int kk=0;kk<8;kk++){
            float ar[8],br[8];
            *(float4*)&ar[0]=*(const float4*)&As[kk][ty*8];
            *(float4*)&ar[4]=*(const float4*)&As[kk][ty*8+4];
            *(float4*)&br[0]=*(const float4*)&Bs[kk][tx*8];
            *(float4*)&br[4]=*(const float4*)&Bs[kk][tx*8+4];
#pragma unroll
            for(int i=0;i<8;i++)
#pragma unroll
                for(int j=0;j<8;j++) acc[i][j]=fmaf(ar[i],br[j],acc[i][j]);
        }
        __syncthreads();
    }
#pragma unroll
    for(int i=0;i<8;i++){
        size_t m=bm+ty*8+i;
#pragma unroll
        for(int j=0;j<8;j+=4){
            int n=bn+tx*8+j;
            float4 o;
            o.x=acc[i][j+0]+bp[n+0]; o.y=acc[i][j+1]+bp[n+1];
            o.z=acc[i][j+2]+bp[n+2]; o.w=acc[i][j+3]+bp[n+3];
            *(float4*)&Cout[m*(size_t)N+n]=o;
        }
    }
}

// transpose g_xw [t][b][2048] -> g_xwT [t][2048][b]
__global__ void transpose_xw(){
    __shared__ float tl[64][33];
    int j0=blockIdx.x*32, t=blockIdx.y;
    for(int f=threadIdx.x; f<2048; f+=256){ int b=f>>5, j=f&31;
        tl[b][j]=g_xw[((size_t)t*64+b)*2048 + j0+j]; }
    __syncthreads();
    for(int f=threadIdx.x; f<2048; f+=256){ int j=f>>6, b=f&63;
        g_xwT[(size_t)t*131072 + (size_t)(j0+j)*64 + b]=tl[b][j]; }
}

// init (absorbs combine_bias)
__global__ void init_state(const float* __restrict__ h0,const float* __restrict__ c0,
                           const float* __restrict__ cov,
                           const float* __restrict__ bi,const float* __restrict__ bh){
    int i=blockIdx.x*256+threadIdx.x;
    if(i<Bc*Hc){ int b=i>>9,u=i&511; g_sT[0][u*64+b]=h0[i]; g_sT[0][(512+u)*64+b]=c0[i]; }
    if(i<Bc*TXc) g_acc[i]=cov[i];
    if(i<G4c) g_bias4[i]=bi[i]+bh[i];
    if(i<NBc*8){ g_flags[i]=0; g_pflags[i]=0; }
}

// ---------------- persistent recurrence (A,B,C,E only) ----------------
__global__ void __launch_bounds__(NTc,1)
decoder_persistent(const float* __restrict__ xmask,const float* __restrict__ ymask,
                   const float* __restrict__ W_hh,const float* __restrict__ W_comb,
                   const float* __restrict__ U_att,const float* __restrict__ W_cov,
                   float* __restrict__ o_hs,float* __restrict__ o_cs,
                   float* __restrict__ o_ss,
                   float* __restrict__ o_dists,float* __restrict__ o_Cs){
    extern __shared__ float sm[];
    const int tid=threadIdx.x, bk=blockIdx.x;
    const int wid=tid>>5, lane=tid&31;
    unsigned gen=0, pgen=0;
    const unsigned long long POL=mk_keep_policy();

    // one-time weight preload
    for(int f=tid;f<8192;f+=NTc){ int jj=f>>9,k=f&511;
        sm[OFF_WHH+jj*520+k]=W_hh[(size_t)((jj>>2)*512+bk*4+(jj&3))*512+k]; }
    for(int f=tid;f<4096;f+=NTc){ int c=f>>10,k=f&1023;
        sm[OFF_WCB+c*1040+k]=W_comb[(size_t)(bk*4+c)*1024+k]; }
    for(int f=tid;f<512;f+=NTc){
        sm[OFF_U+f]=U_att[f]; sm[OFF_WC+f]=W_cov[f]; }
    __syncthreads();

    for(int t=0;t<TYc;t++){
        const int ph=t&1;

        // ===== A: gates = h @ W_hh.T, LSTM cell =====
        __syncthreads();   // protect RED vs E tail of previous step
        {
            const int ks=tid>>6, jg=(tid>>4)&3, bg=tid&15;
            const float* hT=g_sT[ph];
            float acc[4][4]={};
#pragma unroll 2
            for(int kk=0;kk<32;kk+=2){
                int k=ks*32+kk;
                float4 hv0=*(const float4*)&hT[(size_t)k*64+bg*4];
                float4 hv1=*(const float4*)&hT[(size_t)(k+1)*64+bg*4];
#pragma unroll
                for(int ji=0;ji<4;ji++){
                    float2 w=*(const float2*)&sm[OFF_WHH+(jg*4+ji)*520+k];
                    acc[ji][0]=fmaf(w.x,hv0.x,acc[ji][0]);
                    acc[ji][1]=fmaf(w.x,hv0.y,acc[ji][1]);
                    acc[ji][2]=fmaf(w.x,hv0.z,acc[ji][2]);
                    acc[ji][3]=fmaf(w.x,hv0.w,acc[ji][3]);
                    acc[ji][0]=fmaf(w.y,hv1.x,acc[ji][0]);
                    acc[ji][1]=fmaf(w.y,hv1.y,acc[ji][1]);
                    acc[ji][2]=fmaf(w.y,hv1.z,acc[ji][2]);
                    acc[ji][3]=fmaf(w.y,hv1.w,acc[ji][3]);
                }
            }
#pragma unroll
            for(int ji=0;ji<4;ji++)
#pragma unroll
                for(int bi=0;bi<4;bi++)
                    sm[OFF_RED+ks*1024+(jg*4+ji)*64+bg*4+bi]=acc[ji][bi];
            __syncthreads();
            {
                float s=0.f;
#pragma unroll
                for(int k2=0;k2<16;k2++) s+=sm[OFF_RED+k2*1024+tid];
                sm[OFF_GATE+tid]=s;
            }
            __syncthreads();
            if(tid<256){
                int ui=tid>>6, b=tid&63;
                int u=bk*4+ui;
                const float* xwT=&g_xwT[(size_t)t*131072];
                float gi=sm[OFF_GATE+(0*4+ui)*64+b]+ldg_stream(&xwT[(size_t)(0*512+u)*64+b]);
                float gf=sm[OFF_GATE+(1*4+ui)*64+b]+ldg_stream(&xwT[(size_t)(1*512+u)*64+b]);
                float gg=sm[OFF_GATE+(2*4+ui)*64+b]+ldg_stream(&xwT[(size_t)(2*512+u)*64+b]);
                float go=sm[OFF_GATE+(3*4+ui)*64+b]+ldg_stream(&xwT[(size_t)(3*512+u)*64+b]);
                float ho=g_sT[ph][u*64+b];
                float co=g_sT[ph][(512+u)*64+b];
                float c1=sigf(gf)*co+sigf(gi)*tanh_acc(gg);
                float h1=sigf(go)*tanh_acc(c1);
                float m=ymask[t*64+b];
                h1=m*h1+(1.0f-m)*ho;
                c1=m*c1+(1.0f-m)*co;
                g_sT[ph^1][u*64+b]=h1;
                g_sT[ph^1][(512+u)*64+b]=c1;
                size_t oo=((size_t)t*64+b)*512+u;
                stg_stream(&o_hs[oo],h1);
                stg_stream(&o_ss[oo],h1);
                stg_stream(&o_cs[oo],c1);
            }
        }
        gsync(++gen);

        // ===== B: hq = [h,c] @ W_comb.T (K=1024) =====
        {
            const int ks=tid>>6, cl=(tid>>4)&3, bg=tid&15;
            const float* sT=g_sT[ph^1];
            float acc[4]={};
#pragma unroll 4
            for(int kk=0;kk<64;kk++){
                int k=ks*64+kk;
                float4 v=*(const float4*)&sT[(size_t)k*64+bg*4];
                float w=sm[OFF_WCB+cl*1040+k];
                acc[0]=fmaf(w,v.x,acc[0]); acc[1]=fmaf(w,v.y,acc[1]);
                acc[2]=fmaf(w,v.z,acc[2]); acc[3]=fmaf(w,v.w,acc[3]);
            }
#pragma unroll
            for(int bi=0;bi<4;bi++) sm[OFF_RED+ks*256+cl*64+bg*4+bi]=acc[bi];
            __syncthreads();
            if(tid<256){
                int cl2=tid>>6, b=tid&63;
                float s=0.f;
#pragma unroll
                for(int k2=0;k2<16;k2++) s+=sm[OFF_RED+k2*256+tid];
                g_hq[b*512+bk*4+cl2]=s;
            }
        }
        gsync(++gen);

        // ===== C: scores e[b][h][ts] (pctx pinned in L2) =====
        {
            const int b=bk>>1, tb=(bk&1)*200;
            float hqr[16];
#pragma unroll
            for(int ii=0;ii<16;ii++) hqr[ii]=g_hq[b*512+ii*32+lane];
            for(int i=0;i<7;i++){
                int tsl=wid+32*i;
                if(tsl<200){
                    int ts=tb+tsl;
                    float cov=g_acc[b*400+ts];
                    float xm=xmask[ts*64+b];
                    const float* pc=&g_pctx[((size_t)ts*64+b)*512];
                    float a[8]={};
#pragma unroll
                    for(int ii=0;ii<16;ii++){
                        int c=ii*32+lane;
                        float arg=ldg_keep(&pc[c],POL)+hqr[ii]+cov*sm[OFF_WC+c];
                        a[ii>>1]=fmaf(tanh_fast(arg),sm[OFF_U+c],a[ii>>1]);
                    }
#pragma unroll
                    for(int hh=0;hh<8;hh++){
                        float s=a[hh]*xm;
#pragma unroll
                        for(int o=16;o>0;o>>=1) s+=__shfl_xor_sync(0xffffffffu,s,o);
                        if(lane==0) g_e[(b*8+hh)*400+ts]=s;
                    }
                }
            }
        }
        psync(++pgen);   // partner block (same b, other ts half) only

        // ===== E: fused softmax + context -> g_ctxbuf (pv pinned in L2) =====
        {
            const int b=bk>>1, ch=bk&1;
            if(wid<4){
                const int hh=ch*4+wid;
                const float* ep=&g_e[(b*8+hh)*400];
                float ev[13]; float mx=-3.4e38f;
#pragma unroll
                for(int i=0;i<13;i++){ int ts=lane+32*i;
                    float v=(ts<400)?ep[ts]:-3.4e38f; ev[i]=v; mx=fmaxf(mx,v); }
#pragma unroll
                for(int o=16;o>0;o>>=1) mx=fmaxf(mx,__shfl_xor_sync(0xffffffffu,mx,o));
                float sum=0.f;
#pragma unroll
                for(int i=0;i<13;i++){ int ts=lane+32*i;
                    if(ts<400){ float v=__expf(ev[i]-mx)*xmask[ts*64+b]; ev[i]=v; sum+=v; } }
#pragma unroll
                for(int o=16;o>0;o>>=1) sum+=__shfl_xor_sync(0xffffffffu,sum,o);
                float inv=1.0f/(sum+1e-6f);
#pragma unroll
                for(int i=0;i<13;i++){ int ts=lane+32*i;
                    if(ts<400){
                        float w=ev[i]*inv;
                        sm[OFF_SW4+wid*408+ts]=w;
                        if(ch==0&&wid==0){
                            float a=g_acc[b*400+ts];
                            stg_stream(&o_Cs[((size_t)t*64+b)*400+ts],a);
                            stg_stream(&o_dists[((size_t)t*64+b)*400+ts],w);
                            g_acc[b*400+ts]=a+w;
                        }
                    } }
            }
            __syncthreads();
            const int tq=tid>>6, cg=tid&63, hl=cg>>4;
            const int c=ch*256+cg*4;
            const float* pvp=&g_pv[(size_t)b*512+c];
            float a0=0.f,a1=0.f,a2=0.f,a3=0.f;
            int t0=tq*25;
#pragma unroll 5
            for(int tt=0;tt<25;tt++){
                int ts=t0+tt;
                float4 v=ldg_keep4(pvp+(size_t)ts*32768,POL);
                float wv=sm[OFF_SW4+hl*408+ts];
                a0=fmaf(v.x,wv,a0); a1=fmaf(v.y,wv,a1);
                a2=fmaf(v.z,wv,a2); a3=fmaf(v.w,wv,a3);
            }
            sm[OFF_RED+tq*256+cg*4+0]=a0;
            sm[OFF_RED+tq*256+cg*4+1]=a1;
            sm[OFF_RED+tq*256+cg*4+2]=a2;
            sm[OFF_RED+tq*256+cg*4+3]=a3;
            __syncthreads();
            if(tid<256){
                float s=0.f;
#pragma unroll
                for(int k2=0;k2<16;k2++) s+=sm[OFF_RED+k2*256+tid];
                stg_stream(&g_ctxbuf[((size_t)t*64+b)*512 + ch*256+tid],s);
            }
        }
        // no trailing grid barrier (E outputs consumed post-kernel / next-step
        // consumers ordered by the A/B gsyncs)
    }
}

// ---------------- deferred: att = ctx @ W_concat^T (M=8192,N=512,K=512) ----
__global__ void att_gemm(const float* __restrict__ Wcat){
    const int K=512, N=512;
    __shared__ float As[8][128], Bs[8][128];
    int bm=blockIdx.y*128, bn=blockIdx.x*128;
    int tid=threadIdx.x;
    int lr=tid>>1, lc=(tid&1)*4;
    int ty=tid>>4, tx=tid&15;
    float acc[8][8]={};
    const float* Ap=g_ctxbuf+(size_t)(bm+lr)*K+lc;
    const float* Bp=Wcat+(size_t)(bn+lr)*K+lc;
    float4 a4=*(const float4*)(Ap);
    float4 b4=*(const float4*)(Bp);
    for(int k0=0;k0<K;k0+=8){
        As[lc][lr]=a4.x; As[lc+1][lr]=a4.y; As[lc+2][lr]=a4.z; As[lc+3][lr]=a4.w;
        Bs[lc][lr]=b4.x; Bs[lc+1][lr]=b4.y; Bs[lc+2][lr]=b4.z; Bs[lc+3][lr]=b4.w;
        __syncthreads();
        if(k0+8<K){
            a4=*(const float4*)(Ap+k0+8);
            b4=*(const float4*)(Bp+k0+8);
        }
#pragma unroll
        for(int kk=0;kk<8;kk++){
            float ar[8],br[8];
            *(float4*)&ar[0]=*(const float4*)&As[kk][ty*8];
            *(float4*)&ar[4]=*(const float4*)&As[kk][ty*8+4];
            *(float4*)&br[0]=*(const float4*)&Bs[kk][tx*8];
            *(float4*)&br[4]=*(const float4*)&Bs[kk][tx*8+4];
#pragma unroll
            for(int i=0;i<8;i++)
#pragma unroll
                for(int j=0;j<8;j++) acc[i][j]=fmaf(ar[i],br[j],acc[i][j]);
        }
        __syncthreads();
    }
#pragma unroll
    for(int i=0;i<8;i++){
        size_t m=bm+ty*8+i;
#pragma unroll
        for(int j=0;j<8;j+=4){
            *(float4*)&g_attbuf[m*N+bn+tx*8+j]=*(float4*)&acc[i][j];
        }
    }
}

// ---------------- deferred LayerNorm over all 8192 rows ----------------
__global__ void ln_out(const float* __restrict__ lng,const float* __restrict__ lnb,
                       float* __restrict__ o_atts){
    __shared__ float red[16];
    int r=blockIdx.x, tid=threadIdx.x;   // 256 threads
    int lane=tid&31, wd=tid>>5;
    float v0=g_attbuf[(size_t)r*512+tid];
    float v1=g_attbuf[(size_t)r*512+256+tid];
    float s=v0+v1;
#pragma unroll
    for(int o=16;o>0;o>>=1) s+=__shfl_xor_sync(0xffffffffu,s,o);
    if(lane==0) red[wd]=s;
    __syncthreads();
    float mu=0.f;
#pragma unroll
    for(int i=0;i<8;i++) mu+=red[i];
    mu*=(1.0f/512.0f);
    __syncthreads();
    float d0=v0-mu, d1=v1-mu;
    float s2=d0*d0+d1*d1;
#pragma unroll
    for(int o=16;o>0;o>>=1) s2+=__shfl_xor_sync(0xffffffffu,s2,o);
    if(lane==0) red[wd]=s2;
    __syncthreads();
    float var=0.f;
#pragma unroll
    for(int i=0;i<8;i++) var+=red[i];
    var*=(1.0f/512.0f);
    float inv=rsqrtf(var+1e-5f);
    o_atts[(size_t)r*512+tid]     =d0*inv*lng[tid]     +lnb[tid];
    o_atts[(size_t)r*512+256+tid] =d1*inv*lng[256+tid] +lnb[256+tid];
}

extern "C" void kernel_launch(void* const* d_in,const int* in_sizes,int n_in,
                              void* d_out,int out_size){
    const float* y_emb   =(const float*)d_in[0];
    const float* context =(const float*)d_in[1];
    const float* h0      =(const float*)d_in[2];
    const float* c0      =(const float*)d_in[3];
    const float* xmask   =(const float*)d_in[4];
    const float* ymask   =(const float*)d_in[5];
    const float* cov0    =(const float*)d_in[6];
    const float* W_ih    =(const float*)d_in[7];
    const float* W_hh    =(const float*)d_in[8];
    const float* b_ih    =(const float*)d_in[9];
    const float* b_hh    =(const float*)d_in[10];
    const float* Wc_att  =(const float*)d_in[11];
    const float* b_att   =(const float*)d_in[12];
    const float* Wv_att  =(const float*)d_in[13];
    const float* bv_att  =(const float*)d_in[14];
    const float* W_comb  =(const float*)d_in[15];
    const float* U_att   =(const float*)d_in[16];
    const float* W_cov   =(const float*)d_in[17];
    const float* W_concat=(const float*)d_in[18];
    const float* ln_g    =(const float*)d_in[19];
    const float* ln_b    =(const float*)d_in[20];

    float* out    =(float*)d_out;
    float* o_hs   =out;
    float* o_cs   =o_hs+(size_t)TYc*Bc*Hc;
    float* o_ss   =o_cs+(size_t)TYc*Bc*Hc;
    float* o_atts =o_ss+(size_t)TYc*Bc*Hc;
    float* o_dists=o_atts+(size_t)TYc*Bc*Cc;
    float* o_Cs   =o_dists+(size_t)TYc*Bc*TXc;

    // launch order: decoder is my idx 3 (ncu -s 5 with ~2 hidden launches)
    init_state<<<128,256>>>(h0,c0,cov0,b_ih,b_hh);
    mega_sgemm<<<2624,256>>>(context,Wc_att,b_att,Wv_att,bv_att,y_emb,W_ih);
    transpose_xw<<<dim3(64,128),256>>>();

    cudaFuncSetAttribute(decoder_persistent,
        cudaFuncAttributeMaxDynamicSharedMemorySize, SMEM_FLOATS*4);
    decoder_persistent<<<NBc,NTc,SMEM_FLOATS*4>>>(xmask,ymask,W_hh,W_comb,U_att,W_cov,
        o_hs,o_cs,o_ss,o_dists,o_Cs);

    att_gemm<<<dim3(4,64),256>>>(W_concat);
    ln_out<<<TYc*Bc,256>>>(ln_g,ln_b,o_atts);
}

// round 13
// speedup vs baseline: 1.1827x; 1.1827x over previous
#include <cuda_runtime.h>
#include <cuda_fp16.h>
#include <math.h>

constexpr int TYc=128, Bc=64, TXc=400, Hc=512, Cc=512, G4c=2048;
constexpr int NBc=128, NTc=1024;

// ---------------- device scratch ----------------
__device__ float g_pctx[(size_t)TXc*Bc*Cc];
__device__ __align__(16) __half g_pvh[(size_t)TXc*Bc*Cc];   // fp16 value proj
__device__ float g_xw  [(size_t)TYc*Bc*G4c];   // [t][b][4H]
__device__ float g_xwT [(size_t)TYc*G4c*Bc];   // [t][4H][b]
__device__ float g_bias4[G4c];
__device__ float g_sT[2][1024*Bc];             // [k][b]; 0-511=h, 512-1023=c
__device__ float g_hq [Bc*Cc];
__device__ float g_e  [Bc*8*TXc];
__device__ float g_acc[Bc*TXc];
__device__ float g_ctxbuf[(size_t)TYc*Bc*Cc];  // per-step context (deferred F)
__device__ float g_attbuf[(size_t)TYc*Bc*Cc];  // ctx @ W_concat^T (pre-LN)
__device__ volatile unsigned g_flags[NBc*8];   // global barrier slots
__device__ volatile unsigned g_pflags[NBc*8];  // pair barrier slots

// smem layout (floats)
constexpr int OFF_WHH=0;            // 16x520 = 8320
constexpr int OFF_WCB=8320;         // 4x1040 = 4160
constexpr int OFF_U  =12480;        // 512
constexpr int OFF_WC =12992;        // 512
constexpr int OFF_RED=13504;        // 16384
constexpr int OFF_GATE=29888;       // 1024
constexpr int OFF_SW4=30912;        // 4x408 = 1632
constexpr int SMEM_FLOATS=32544;    // ~130KB

__device__ __forceinline__ float sigf(float x){ return 1.0f/(1.0f+__expf(-x)); }
__device__ __forceinline__ float tanh_acc(float x){
    float e=__expf(2.0f*fabsf(x));
    float r=1.0f-2.0f/(e+1.0f);
    return copysignf(r,x);
}
__device__ __forceinline__ float tanh_fast(float x){
    float r; asm("tanh.approx.f32 %0,%1;":"=f"(r):"f"(x)); return r;
}

// ---- flag-based all-to-all grid barrier ----
__device__ __forceinline__ void gsync(unsigned gen){
    __syncthreads();
    if(threadIdx.x==0){ __threadfence(); g_flags[blockIdx.x*8]=gen; }
    if(threadIdx.x<NBc){
        while(g_flags[threadIdx.x*8]<gen){}
    }
    __syncthreads();
    if(threadIdx.x==0) __threadfence();   // drop stale L1 lines
    __syncthreads();
}
// ---- 2-block pair barrier (partner = bk^1) ----
__device__ __forceinline__ void psync(unsigned gen){
    __syncthreads();
    if(threadIdx.x==0){
        __threadfence();
        g_pflags[blockIdx.x*8]=gen;
        while(g_pflags[(blockIdx.x^1)*8]<gen){}
        __threadfence();
    }
    __syncthreads();
}

// ---------------- ONE flattened precompute GEMM (3 sub-problems) -----------
// C[m][n]=sum_k A[m][k]*B[n][k]+bias[n], K=512. Double-buffered.
__global__ void mega_sgemm(const float* __restrict__ ctx,
                           const float* __restrict__ Wc,const float* __restrict__ bc,
                           const float* __restrict__ Wv,const float* __restrict__ bv,
                           const float* __restrict__ yemb,const float* __restrict__ Wih){
    const int K=512;
    int bid=blockIdx.x;
    const float *A,*Bm,*bp; float* Cout=nullptr; __half* Hout=nullptr;
    int N,bm,bn;
    if(bid<800){        A=ctx;  Bm=Wc;  bp=bc;      Cout=g_pctx; N=512;
                        bm=(bid>>2)*128; bn=(bid&3)*128; }
    else if(bid<1600){  int l=bid-800;
                        A=ctx;  Bm=Wv;  bp=bv;      Hout=g_pvh;  N=512;
                        bm=(l>>2)*128; bn=(l&3)*128; }
    else {              int l=bid-1600;
                        A=yemb; Bm=Wih; bp=g_bias4; Cout=g_xw;   N=2048;
                        bm=(l>>4)*128; bn=(l&15)*128; }
    __shared__ float As[8][128], Bs[8][128];
    int tid=threadIdx.x;
    int lr=tid>>1, lc=(tid&1)*4;
    int ty=tid>>4, tx=tid&15;
    float acc[8][8]={};
    const float* Ap=A+(size_t)(bm+lr)*K+lc;
    const float* Bp=Bm+(size_t)(bn+lr)*K+lc;
    float4 a4=*(const float4*)(Ap);
    float4 b4=*(const float4*)(Bp);
    for(int k0=0;k0<K;k0+=8){
        As[lc][lr]=a4.x; As[lc+1][lr]=a4.y; As[lc+2][lr]=a4.z; As[lc+3][lr]=a4.w;
        Bs[lc][lr]=b4.x; Bs[lc+1][lr]=b4.y; Bs[lc+2][lr]=b4.z; Bs[lc+3][lr]=b4.w;
        __syncthreads();
        if(k0+8<K){                       // prefetch next tile during compute
            a4=*(const float4*)(Ap+k0+8);
            b4=*(const float4*)(Bp+k0+8);
        }
#pragma unroll
        for(int kk=0;kk<8;kk++){
            float ar[8],br[8];
            *(float4*)&ar[0]=*(const float4*)&As[kk][ty*8];
            *(float4*)&ar[4]=*(const float4*)&As[kk][ty*8+4];
            *(float4*)&br[0]=*(const float4*)&Bs[kk][tx*8];
            *(float4*)&br[4]=*(const float4*)&Bs[kk][tx*8+4];
#pragma unroll
            for(int i=0;i<8;i++)
#pragma unroll
                for(int j=0;j<8;j++) acc[i][j]=fmaf(ar[i],br[j],acc[i][j]);
        }
        __syncthreads();
    }
#pragma unroll
    for(int i=0;i<8;i++){
        size_t m=bm+ty*8+i;
#pragma unroll
        for(int j=0;j<8;j+=4){
            int n=bn+tx*8+j;
            float4 o;
            o.x=acc[i][j+0]+bp[n+0]; o.y=acc[i][j+1]+bp[n+1];
            o.z=acc[i][j+2]+bp[n+2]; o.w=acc[i][j+3]+bp[n+3];
            if(Hout){
                __half2 p0=__floats2half2_rn(o.x,o.y);
                __half2 p1=__floats2half2_rn(o.z,o.w);
                uint2 raw;
                raw.x=*(unsigned*)&p0; raw.y=*(unsigned*)&p1;
                *(uint2*)&Hout[m*(size_t)N+n]=raw;
            } else {
                *(float4*)&Cout[m*(size_t)N+n]=o;
            }
        }
    }
}

// transpose g_xw [t][b][2048] -> g_xwT [t][2048][b]
__global__ void transpose_xw(){
    __shared__ float tl[64][33];
    int j0=blockIdx.x*32, t=blockIdx.y;
    for(int f=threadIdx.x; f<2048; f+=256){ int b=f>>5, j=f&31;
        tl[b][j]=g_xw[((size_t)t*64+b)*2048 + j0+j]; }
    __syncthreads();
    for(int f=threadIdx.x; f<2048; f+=256){ int j=f>>6, b=f&63;
        g_xwT[(size_t)t*131072 + (size_t)(j0+j)*64 + b]=tl[b][j]; }
}

// init (absorbs combine_bias)
__global__ void init_state(const float* __restrict__ h0,const float* __restrict__ c0,
                           const float* __restrict__ cov,
                           const float* __restrict__ bi,const float* __restrict__ bh){
    int i=blockIdx.x*256+threadIdx.x;
    if(i<Bc*Hc){ int b=i>>9,u=i&511; g_sT[0][u*64+b]=h0[i]; g_sT[0][(512+u)*64+b]=c0[i]; }
    if(i<Bc*TXc) g_acc[i]=cov[i];
    if(i<G4c) g_bias4[i]=bi[i]+bh[i];
    if(i<NBc*8){ g_flags[i]=0; g_pflags[i]=0; }
}

// ---------------- persistent recurrence (A,B,C,E only) ----------------
__global__ void __launch_bounds__(NTc,1)
decoder_persistent(const float* __restrict__ xmask,const float* __restrict__ ymask,
                   const float* __restrict__ W_hh,const float* __restrict__ W_comb,
                   const float* __restrict__ U_att,const float* __restrict__ W_cov,
                   float* __restrict__ o_hs,float* __restrict__ o_cs,
                   float* __restrict__ o_ss,
                   float* __restrict__ o_dists,float* __restrict__ o_Cs){
    extern __shared__ float sm[];
    const int tid=threadIdx.x, bk=blockIdx.x;
    const int wid=tid>>5, lane=tid&31;
    unsigned gen=0, pgen=0;

    // one-time weight preload
    for(int f=tid;f<8192;f+=NTc){ int jj=f>>9,k=f&511;
        sm[OFF_WHH+jj*520+k]=W_hh[(size_t)((jj>>2)*512+bk*4+(jj&3))*512+k]; }
    for(int f=tid;f<4096;f+=NTc){ int c=f>>10,k=f&1023;
        sm[OFF_WCB+c*1040+k]=W_comb[(size_t)(bk*4+c)*1024+k]; }
    for(int f=tid;f<512;f+=NTc){
        sm[OFF_U+f]=U_att[f]; sm[OFF_WC+f]=W_cov[f]; }
    __syncthreads();

    for(int t=0;t<TYc;t++){
        const int ph=t&1;

        // ===== A: gates = h @ W_hh.T, LSTM cell =====
        __syncthreads();   // protect RED vs E tail of previous step
        {
            const int ks=tid>>6, jg=(tid>>4)&3, bg=tid&15;
            const float* hT=g_sT[ph];
            float acc[4][4]={};
#pragma unroll 2
            for(int kk=0;kk<32;kk+=2){
                int k=ks*32+kk;
                float4 hv0=*(const float4*)&hT[(size_t)k*64+bg*4];
                float4 hv1=*(const float4*)&hT[(size_t)(k+1)*64+bg*4];
#pragma unroll
                for(int ji=0;ji<4;ji++){
                    float2 w=*(const float2*)&sm[OFF_WHH+(jg*4+ji)*520+k];
                    acc[ji][0]=fmaf(w.x,hv0.x,acc[ji][0]);
                    acc[ji][1]=fmaf(w.x,hv0.y,acc[ji][1]);
                    acc[ji][2]=fmaf(w.x,hv0.z,acc[ji][2]);
                    acc[ji][3]=fmaf(w.x,hv0.w,acc[ji][3]);
                    acc[ji][0]=fmaf(w.y,hv1.x,acc[ji][0]);
                    acc[ji][1]=fmaf(w.y,hv1.y,acc[ji][1]);
                    acc[ji][2]=fmaf(w.y,hv1.z,acc[ji][2]);
                    acc[ji][3]=fmaf(w.y,hv1.w,acc[ji][3]);
                }
            }
#pragma unroll
            for(int ji=0;ji<4;ji++)
#pragma unroll
                for(int bi=0;bi<4;bi++)
                    sm[OFF_RED+ks*1024+(jg*4+ji)*64+bg*4+bi]=acc[ji][bi];
            __syncthreads();
            {
                float s=0.f;
#pragma unroll
                for(int k2=0;k2<16;k2++) s+=sm[OFF_RED+k2*1024+tid];
                sm[OFF_GATE+tid]=s;
            }
            __syncthreads();
            if(tid<256){
                int ui=tid>>6, b=tid&63;
                int u=bk*4+ui;
                const float* xwT=&g_xwT[(size_t)t*131072];
                float gi=sm[OFF_GATE+(0*4+ui)*64+b]+xwT[(size_t)(0*512+u)*64+b];
                float gf=sm[OFF_GATE+(1*4+ui)*64+b]+xwT[(size_t)(1*512+u)*64+b];
                float gg=sm[OFF_GATE+(2*4+ui)*64+b]+xwT[(size_t)(2*512+u)*64+b];
                float go=sm[OFF_GATE+(3*4+ui)*64+b]+xwT[(size_t)(3*512+u)*64+b];
                float ho=g_sT[ph][u*64+b];
                float co=g_sT[ph][(512+u)*64+b];
                float c1=sigf(gf)*co+sigf(gi)*tanh_acc(gg);
                float h1=sigf(go)*tanh_acc(c1);
                float m=ymask[t*64+b];
                h1=m*h1+(1.0f-m)*ho;
                c1=m*c1+(1.0f-m)*co;
                g_sT[ph^1][u*64+b]=h1;
                g_sT[ph^1][(512+u)*64+b]=c1;
                size_t oo=((size_t)t*64+b)*512+u;
                o_hs[oo]=h1; o_ss[oo]=h1; o_cs[oo]=c1;
            }
        }
        gsync(++gen);

        // ===== B: hq = [h,c] @ W_comb.T (K=1024) =====
        {
            const int ks=tid>>6, cl=(tid>>4)&3, bg=tid&15;
            const float* sT=g_sT[ph^1];
            float acc[4]={};
#pragma unroll 4
            for(int kk=0;kk<64;kk++){
                int k=ks*64+kk;
                float4 v=*(const float4*)&sT[(size_t)k*64+bg*4];
                float w=sm[OFF_WCB+cl*1040+k];
                acc[0]=fmaf(w,v.x,acc[0]); acc[1]=fmaf(w,v.y,acc[1]);
                acc[2]=fmaf(w,v.z,acc[2]); acc[3]=fmaf(w,v.w,acc[3]);
            }
#pragma unroll
            for(int bi=0;bi<4;bi++) sm[OFF_RED+ks*256+cl*64+bg*4+bi]=acc[bi];
            __syncthreads();
            if(tid<256){
                int cl2=tid>>6, b=tid&63;
                float s=0.f;
#pragma unroll
                for(int k2=0;k2<16;k2++) s+=sm[OFF_RED+k2*256+tid];
                g_hq[b*512+bk*4+cl2]=s;
            }
        }
        gsync(++gen);

        // ===== C: scores e[b][h][ts] =====
        {
            const int b=bk>>1, tb=(bk&1)*200;
            float hqr[16];
#pragma unroll
            for(int ii=0;ii<16;ii++) hqr[ii]=g_hq[b*512+ii*32+lane];
            for(int i=0;i<7;i++){
                int tsl=wid+32*i;
                if(tsl<200){
                    int ts=tb+tsl;
                    float cov=g_acc[b*400+ts];
                    float xm=xmask[ts*64+b];
                    const float* pc=&g_pctx[((size_t)ts*64+b)*512];
                    float a[8]={};
#pragma unroll
                    for(int ii=0;ii<16;ii++){
                        int c=ii*32+lane;
                        float arg=pc[c]+hqr[ii]+cov*sm[OFF_WC+c];
                        a[ii>>1]=fmaf(tanh_fast(arg),sm[OFF_U+c],a[ii>>1]);
                    }
#pragma unroll
                    for(int hh=0;hh<8;hh++){
                        float s=a[hh]*xm;
#pragma unroll
                        for(int o=16;o>0;o>>=1) s+=__shfl_xor_sync(0xffffffffu,s,o);
                        if(lane==0) g_e[(b*8+hh)*400+ts]=s;
                    }
                }
            }
        }
        psync(++pgen);   // partner block (same b, other ts half) only

        // ===== E: fused softmax + context -> g_ctxbuf (pv fp16) =====
        {
            const int b=bk>>1, ch=bk&1;
            if(wid<4){
                const int hh=ch*4+wid;
                const float* ep=&g_e[(b*8+hh)*400];
                float ev[13]; float mx=-3.4e38f;
#pragma unroll
                for(int i=0;i<13;i++){ int ts=lane+32*i;
                    float v=(ts<400)?ep[ts]:-3.4e38f; ev[i]=v; mx=fmaxf(mx,v); }
#pragma unroll
                for(int o=16;o>0;o>>=1) mx=fmaxf(mx,__shfl_xor_sync(0xffffffffu,mx,o));
                float sum=0.f;
#pragma unroll
                for(int i=0;i<13;i++){ int ts=lane+32*i;
                    if(ts<400){ float v=__expf(ev[i]-mx)*xmask[ts*64+b]; ev[i]=v; sum+=v; } }
#pragma unroll
                for(int o=16;o>0;o>>=1) sum+=__shfl_xor_sync(0xffffffffu,sum,o);
                float inv=1.0f/(sum+1e-6f);
#pragma unroll
                for(int i=0;i<13;i++){ int ts=lane+32*i;
                    if(ts<400){
                        float w=ev[i]*inv;
                        sm[OFF_SW4+wid*408+ts]=w;
                        if(ch==0&&wid==0){
                            float a=g_acc[b*400+ts];
                            o_Cs[((size_t)t*64+b)*400+ts]=a;
                            o_dists[((size_t)t*64+b)*400+ts]=w;
                            g_acc[b*400+ts]=a+w;
                        }
                    } }
            }
            __syncthreads();
            const int tq=tid>>6, cg=tid&63, hl=cg>>4;
            const int c=ch*256+cg*4;
            const __half* pvp=&g_pvh[(size_t)b*512+c];
            float a0=0.f,a1=0.f,a2=0.f,a3=0.f;
            int t0=tq*25;
#pragma unroll 5
            for(int tt=0;tt<25;tt++){
                int ts=t0+tt;
                uint2 raw=*(const uint2*)(pvp+(size_t)ts*32768);
                float2 f01=__half22float2(*(__half2*)&raw.x);
                float2 f23=__half22float2(*(__half2*)&raw.y);
                float wv=sm[OFF_SW4+hl*408+ts];
                a0=fmaf(f01.x,wv,a0); a1=fmaf(f01.y,wv,a1);
                a2=fmaf(f23.x,wv,a2); a3=fmaf(f23.y,wv,a3);
            }
            sm[OFF_RED+tq*256+cg*4+0]=a0;
            sm[OFF_RED+tq*256+cg*4+1]=a1;
            sm[OFF_RED+tq*256+cg*4+2]=a2;
            sm[OFF_RED+tq*256+cg*4+3]=a3;
            __syncthreads();
            if(tid<256){
                float s=0.f;
#pragma unroll
                for(int k2=0;k2<16;k2++) s+=sm[OFF_RED+k2*256+tid];
                g_ctxbuf[((size_t)t*64+b)*512 + ch*256+tid]=s;
            }
        }
        // no trailing grid barrier (E outputs consumed post-kernel / next-step
        // consumers ordered by the A/B gsyncs)
    }
}

// ---------------- deferred: att = ctx @ W_concat^T (M=8192,N=512,K=512) ----
__global__ void att_gemm(const float* __restrict__ Wcat){
    const int K=512, N=512;
    __shared__ float As[8][128], Bs[8][128];
    int bm=blockIdx.y*128, bn=blockIdx.x*128;
    int tid=threadIdx.x;
    int lr=tid>>1, lc=(tid&1)*4;
    int ty=tid>>4, tx=tid&15;
    float acc[8][8]={};
    const float* Ap=g_ctxbuf+(size_t)(bm+lr)*K+lc;
    const float* Bp=Wcat+(size_t)(bn+lr)*K+lc;
    float4 a4=*(const float4*)(Ap);
    float4 b4=*(const float4*)(Bp);
    for(int k0=0;k0<K;k0+=8){
        As[lc][lr]=a4.x; As[lc+1][lr]=a4.y; As[lc+2][lr]=a4.z; As[lc+3][lr]=a4.w;
        Bs[lc][lr]=b4.x; Bs[lc+1][lr]=b4.y; Bs[lc+2][lr]=b4.z; Bs[lc+3][lr]=b4.w;
        __syncthreads();
        if(k0+8<K){
            a4=*(const float4*)(Ap+k0+8);
            b4=*(const float4*)(Bp+k0+8);
        }
#pragma unroll
        for(int kk=0;kk<8;kk++){
            float ar[8],br[8];
            *(float4*)&ar[0]=*(const float4*)&As[kk][ty*8];
            *(float4*)&ar[4]=*(const float4*)&As[kk][ty*8+4];
            *(float4*)&br[0]=*(const float4*)&Bs[kk][tx*8];
            *(float4*)&br[4]=*(const float4*)&Bs[kk][tx*8+4];
#pragma unroll
            for(int i=0;i<8;i++)
#pragma unroll
                for(int j=0;j<8;j++) acc[i][j]=fmaf(ar[i],br[j],acc[i][j]);
        }
        __syncthreads();
    }
#pragma unroll
    for(int i=0;i<8;i++){
        size_t m=bm+ty*8+i;
#pragma unroll
        for(int j=0;j<8;j+=4){
            *(float4*)&g_attbuf[m*N+bn+tx*8+j]=*(float4*)&acc[i][j];
        }
    }
}

// ---------------- deferred LayerNorm over all 8192 rows ----------------
__global__ void ln_out(const float* __restrict__ lng,const float* __restrict__ lnb,
                       float* __restrict__ o_atts){
    __shared__ float red[16];
    int r=blockIdx.x, tid=threadIdx.x;   // 256 threads
    int lane=tid&31, wd=tid>>5;
    float v0=g_attbuf[(size_t)r*512+tid];
    float v1=g_attbuf[(size_t)r*512+256+tid];
    float s=v0+v1;
#pragma unroll
    for(int o=16;o>0;o>>=1) s+=__shfl_xor_sync(0xffffffffu,s,o);
    if(lane==0) red[wd]=s;
    __syncthreads();
    float mu=0.f;
#pragma unroll
    for(int i=0;i<8;i++) mu+=red[i];
    mu*=(1.0f/512.0f);
    __syncthreads();
    float d0=v0-mu, d1=v1-mu;
    float s2=d0*d0+d1*d1;
#pragma unroll
    for(int o=16;o>0;o>>=1) s2+=__shfl_xor_sync(0xffffffffu,s2,o);
    if(lane==0) red[wd]=s2;
    __syncthreads();
    float var=0.f;
#pragma unroll
    for(int i=0;i<8;i++) var+=red[i];
    var*=(1.0f/512.0f);
    float inv=rsqrtf(var+1e-5f);
    o_atts[(size_t)r*512+tid]     =d0*inv*lng[tid]     +lnb[tid];
    o_atts[(size_t)r*512+256+tid] =d1*inv*lng[256+tid] +lnb[256+tid];
}

extern "C" void kernel_launch(void* const* d_in,const int* in_sizes,int n_in,
                              void* d_out,int out_size){
    const float* y_emb   =(const float*)d_in[0];
    const float* context =(const float*)d_in[1];
    const float* h0      =(const float*)d_in[2];
    const float* c0      =(const float*)d_in[3];
    const float* xmask   =(const float*)d_in[4];
    const float* ymask   =(const float*)d_in[5];
    const float* cov0    =(const float*)d_in[6];
    const float* W_ih    =(const float*)d_in[7];
    const float* W_hh    =(const float*)d_in[8];
    const float* b_ih    =(const float*)d_in[9];
    const float* b_hh    =(const float*)d_in[10];
    const float* Wc_att  =(const float*)d_in[11];
    const float* b_att   =(const float*)d_in[12];
    const float* Wv_att  =(const float*)d_in[13];
    const float* bv_att  =(const float*)d_in[14];
    const float* W_comb  =(const float*)d_in[15];
    const float* U_att   =(const float*)d_in[16];
    const float* W_cov   =(const float*)d_in[17];
    const float* W_concat=(const float*)d_in[18];
    const float* ln_g    =(const float*)d_in[19];
    const float* ln_b    =(const float*)d_in[20];

    float* out    =(float*)d_out;
    float* o_hs   =out;
    float* o_cs   =o_hs+(size_t)TYc*Bc*Hc;
    float* o_ss   =o_cs+(size_t)TYc*Bc*Hc;
    float* o_atts =o_ss+(size_t)TYc*Bc*Hc;
    float* o_dists=o_atts+(size_t)TYc*Bc*Cc;
    float* o_Cs   =o_dists+(size_t)TYc*Bc*TXc;

    init_state<<<128,256>>>(h0,c0,cov0,b_ih,b_hh);
    mega_sgemm<<<2624,256>>>(context,Wc_att,b_att,Wv_att,bv_att,y_emb,W_ih);
    transpose_xw<<<dim3(64,128),256>>>();

    cudaFuncSetAttribute(decoder_persistent,
        cudaFuncAttributeMaxDynamicSharedMemorySize, SMEM_FLOATS*4);
    decoder_persistent<<<NBc,NTc,SMEM_FLOATS*4>>>(xmask,ymask,W_hh,W_comb,U_att,W_cov,
        o_hs,o_cs,o_ss,o_dists,o_Cs);

    att_gemm<<<dim3(4,64),256>>>(W_concat);
    ln_out<<<TYc*Bc,256>>>(ln_g,ln_b,o_atts);
}